// round 2
// baseline (speedup 1.0000x reference)
#include <cuda_runtime.h>

// Problem dims (fixed by the dataset)
#define BB 4
#define TT 256
#define UU 128
#define HH 512
#define VV 1024

// Scratch (module-load allocated; no runtime allocs)
__device__ float g_e[BB * TT * HH];                 // 2 MB
__device__ float g_d[BB * UU * HH];                 // 1 MB
__device__ float g_j[(size_t)BB * TT * UU * HH];    // 256 MB

// ---------------- f32x2 packed-FMA helpers (sm_100+) ----------------
__device__ __forceinline__ unsigned long long ffma2(unsigned long long a,
                                                    unsigned long long b,
                                                    unsigned long long c) {
    unsigned long long d;
    asm("fma.rn.f32x2 %0, %1, %2, %3;" : "=l"(d) : "l"(a), "l"(b), "l"(c));
    return d;
}
__device__ __forceinline__ unsigned long long pack2(float lo, float hi) {
    unsigned long long r;
    asm("mov.b64 %0, {%1, %2};" : "=l"(r) : "f"(lo), "f"(hi));
    return r;
}
__device__ __forceinline__ float2 unpack2(unsigned long long v) {
    float2 r;
    asm("mov.b64 {%0, %1}, %2;" : "=f"(r.x), "=f"(r.y) : "l"(v));
    return r;
}
__device__ __forceinline__ float tanh_apx(float x) {
    float y;
    asm("tanh.approx.f32 %0, %1;" : "=f"(y) : "f"(x));
    return y;
}

// ---------------- generic SGEMM: C[m][n] = sum_k A[m][k]*W[n][k] + bias[n] ----
// Tiles: 128(M) x 128(N) x 16(K). 256 threads, each computes an 8x8 microtile
// split as rows {m0..m0+3, m0+64..m0+67} x cols {n0..n0+3, n0+64..n0+67}.
// M,N multiples of 128; K multiple of 16. Uses packed f32x2 FMAs.
__global__ __launch_bounds__(256, 2) void sgemm_bias(
    const float* __restrict__ A, const float* __restrict__ W,
    const float* __restrict__ bias, float* __restrict__ C,
    int M, int N, int K)
{
    __shared__ float As[16][132];
    __shared__ float Bs[16][132];

    const int t = threadIdx.x;
    const int nBase = blockIdx.x * 128;
    const int mBase = blockIdx.y * 128;

    const int m0 = (t >> 4) * 4;   // 0..60
    const int n0 = (t & 15) * 4;   // 0..60

    // loader: 512 float4 per tile per matrix; thread handles rows lrow, lrow+64
    const int lrow = t >> 2;        // 0..63
    const int lcol = (t & 3) * 4;   // k offset within tile: 0,4,8,12

    unsigned long long acc[8][4];
#pragma unroll
    for (int i = 0; i < 8; i++)
#pragma unroll
        for (int jj = 0; jj < 4; jj++) acc[i][jj] = 0ULL;

    const float* Aptr0 = A + (size_t)(mBase + lrow) * K + lcol;
    const float* Aptr1 = A + (size_t)(mBase + lrow + 64) * K + lcol;
    const float* Wptr0 = W + (size_t)(nBase + lrow) * K + lcol;
    const float* Wptr1 = W + (size_t)(nBase + lrow + 64) * K + lcol;

    for (int k0 = 0; k0 < K; k0 += 16) {
        float4 a0 = *(const float4*)(Aptr0 + k0);
        float4 a1 = *(const float4*)(Aptr1 + k0);
        float4 b0 = *(const float4*)(Wptr0 + k0);
        float4 b1 = *(const float4*)(Wptr1 + k0);
        __syncthreads();  // previous tile's compute done before overwrite
        As[lcol + 0][lrow] = a0.x; As[lcol + 1][lrow] = a0.y;
        As[lcol + 2][lrow] = a0.z; As[lcol + 3][lrow] = a0.w;
        As[lcol + 0][lrow + 64] = a1.x; As[lcol + 1][lrow + 64] = a1.y;
        As[lcol + 2][lrow + 64] = a1.z; As[lcol + 3][lrow + 64] = a1.w;
        Bs[lcol + 0][lrow] = b0.x; Bs[lcol + 1][lrow] = b0.y;
        Bs[lcol + 2][lrow] = b0.z; Bs[lcol + 3][lrow] = b0.w;
        Bs[lcol + 0][lrow + 64] = b1.x; Bs[lcol + 1][lrow + 64] = b1.y;
        Bs[lcol + 2][lrow + 64] = b1.z; Bs[lcol + 3][lrow + 64] = b1.w;
        __syncthreads();

#pragma unroll
        for (int k = 0; k < 16; k++) {
            float4 av0 = *(const float4*)&As[k][m0];
            float4 av1 = *(const float4*)&As[k][m0 + 64];
            float4 bv0 = *(const float4*)&Bs[k][n0];
            float4 bv1 = *(const float4*)&Bs[k][n0 + 64];
            unsigned long long bp[4];
            bp[0] = pack2(bv0.x, bv0.y);
            bp[1] = pack2(bv0.z, bv0.w);
            bp[2] = pack2(bv1.x, bv1.y);
            bp[3] = pack2(bv1.z, bv1.w);
            float am[8] = {av0.x, av0.y, av0.z, av0.w,
                           av1.x, av1.y, av1.z, av1.w};
#pragma unroll
            for (int i = 0; i < 8; i++) {
                unsigned long long ad = pack2(am[i], am[i]);
#pragma unroll
                for (int jj = 0; jj < 4; jj++)
                    acc[i][jj] = ffma2(ad, bp[jj], acc[i][jj]);
            }
        }
    }

    // epilogue: + bias, vectorized stores
    float4 bias0 = *(const float4*)(bias + nBase + n0);
    float4 bias1 = *(const float4*)(bias + nBase + n0 + 64);
#pragma unroll
    for (int i = 0; i < 8; i++) {
        const int mg = mBase + m0 + ((i < 4) ? i : (i + 60));  // +64 block
        float2 p0 = unpack2(acc[i][0]);
        float2 p1 = unpack2(acc[i][1]);
        float2 p2 = unpack2(acc[i][2]);
        float2 p3 = unpack2(acc[i][3]);
        float4 o0 = make_float4(p0.x + bias0.x, p0.y + bias0.y,
                                p1.x + bias0.z, p1.y + bias0.w);
        float4 o1 = make_float4(p2.x + bias1.x, p2.y + bias1.y,
                                p3.x + bias1.z, p3.y + bias1.w);
        float* crow = C + (size_t)mg * N + nBase;
        *(float4*)(crow + n0) = o0;
        *(float4*)(crow + n0 + 64) = o1;
    }
}

// ---------------- j = tanh(e[bt] + d[b,u]) materialization ----------------
// One float4 (4 h-values) per thread. 67.1M elements -> 16.8M threads.
__global__ __launch_bounds__(256) void tanh_join_kernel(
    const float* __restrict__ e, const float* __restrict__ d,
    float* __restrict__ j)
{
    const int g = blockIdx.x * blockDim.x + threadIdx.x;  // float4 index
    const int h4 = g & 127;        // H/4 = 128
    const int m = g >> 7;          // bt*U + u
    const int u = m & 127;         // U = 128
    const int bt = m >> 7;
    const int b = bt >> 8;         // T = 256

    float4 ev = ((const float4*)e)[bt * 128 + h4];
    float4 dv = ((const float4*)d)[(b * 128 + u) * 128 + h4];
    float4 o;
    o.x = tanh_apx(ev.x + dv.x);
    o.y = tanh_apx(ev.y + dv.y);
    o.z = tanh_apx(ev.z + dv.z);
    o.w = tanh_apx(ev.w + dv.w);
    ((float4*)j)[(size_t)g] = o;
}

extern "C" void kernel_launch(void* const* d_in, const int* in_sizes, int n_in,
                              void* d_out, int out_size)
{
    const float* enc    = (const float*)d_in[0];  // [B,T,512]
    const float* dec    = (const float*)d_in[1];  // [B,U,512]
    const float* W_enc  = (const float*)d_in[2];  // [512,512]
    const float* b_enc  = (const float*)d_in[3];
    const float* W_dec  = (const float*)d_in[4];
    const float* b_dec  = (const float*)d_in[5];
    const float* W_joint= (const float*)d_in[6];  // [1024,512]
    const float* b_joint= (const float*)d_in[7];
    float* out = (float*)d_out;                   // [B,T,U,1024]

    float *e_ptr, *d_ptr, *j_ptr;
    cudaGetSymbolAddress((void**)&e_ptr, g_e);
    cudaGetSymbolAddress((void**)&d_ptr, g_d);
    cudaGetSymbolAddress((void**)&j_ptr, g_j);

    // e = enc @ W_enc^T + b_enc : M=1024, N=512, K=512
    sgemm_bias<<<dim3(512 / 128, (BB * TT) / 128), 256>>>(
        enc, W_enc, b_enc, e_ptr, BB * TT, HH, 512);
    // d = dec @ W_dec^T + b_dec : M=512, N=512, K=512
    sgemm_bias<<<dim3(512 / 128, (BB * UU) / 128), 256>>>(
        dec, W_dec, b_dec, d_ptr, BB * UU, HH, 512);
    // j = tanh(e broadcast+ d) : 67.1M elems
    tanh_join_kernel<<<(BB * TT * UU * HH / 4) / 256, 256>>>(e_ptr, d_ptr, j_ptr);
    // out = j @ W_joint^T + b_joint : M=131072, N=1024, K=512
    sgemm_bias<<<dim3(VV / 128, (BB * TT * UU) / 128), 256>>>(
        j_ptr, W_joint, b_joint, out, BB * TT * UU, VV, HH);
}

// round 4
// speedup vs baseline: 1.3789x; 1.3789x over previous
#include <cuda_runtime.h>
#include <cuda_bf16.h>
#include <cstdint>

// Problem dims (fixed by the dataset)
#define BB 4
#define TT 256
#define UU 128
#define HH 512
#define VV 1024
#define MM (BB * TT * UU)   // 131072

// ---------------- scratch (module-load allocated) ----------------
__device__ float g_e[BB * TT * HH];                    // 2 MB
__device__ float g_d[BB * UU * HH];                    // 1 MB
// A fragments: [fm (8192)][fk (32)][lane (32)] x 16B   (134 MB each)
__device__ uint4 g_Ahi[(size_t)(MM / 16) * (HH / 16) * 32];
__device__ uint4 g_Alo[(size_t)(MM / 16) * (HH / 16) * 32];
// B fragments: [fn (128)][fk (32)][lane (32)] x 8B     (1 MB each)
__device__ uint2 g_Bhi[(VV / 8) * (HH / 16) * 32];
__device__ uint2 g_Blo[(VV / 8) * (HH / 16) * 32];

// ---------------- helpers ----------------
__device__ __forceinline__ float tanh_apx(float x) {
    float y;
    asm("tanh.approx.f32 %0, %1;" : "=f"(y) : "f"(x));
    return y;
}
// pack {lower = a, upper = b} as bf16x2
__device__ __forceinline__ uint32_t cvt_bf16x2(float a_low, float b_high) {
    uint32_t r;
    asm("cvt.rn.bf16x2.f32 %0, %1, %2;" : "=r"(r) : "f"(b_high), "f"(a_low));
    return r;
}
__device__ __forceinline__ unsigned long long ffma2(unsigned long long a,
                                                    unsigned long long b,
                                                    unsigned long long c) {
    unsigned long long d;
    asm("fma.rn.f32x2 %0, %1, %2, %3;" : "=l"(d) : "l"(a), "l"(b), "l"(c));
    return d;
}
__device__ __forceinline__ unsigned long long pack2(float lo, float hi) {
    unsigned long long r;
    asm("mov.b64 %0, {%1, %2};" : "=l"(r) : "f"(lo), "f"(hi));
    return r;
}
__device__ __forceinline__ float2 unpack2(unsigned long long v) {
    float2 r;
    asm("mov.b64 {%0, %1}, %2;" : "=f"(r.x), "=f"(r.y) : "l"(v));
    return r;
}
// m16n8k16 row.col bf16 -> f32 accumulate (baseline PTX, sm_80+)
__device__ __forceinline__ void mma16816(float* c, const uint32_t* a,
                                         const uint32_t* b) {
    asm volatile(
        "mma.sync.aligned.m16n8k16.row.col.f32.bf16.bf16.f32 "
        "{%0,%1,%2,%3}, {%4,%5,%6,%7}, {%8,%9}, {%0,%1,%2,%3};"
        : "+f"(c[0]), "+f"(c[1]), "+f"(c[2]), "+f"(c[3])
        : "r"(a[0]), "r"(a[1]), "r"(a[2]), "r"(a[3]), "r"(b[0]), "r"(b[1]));
}

// ---------------- small fp32 SGEMM (projections, proven in R1) ----------------
__global__ __launch_bounds__(256, 2) void sgemm_bias(
    const float* __restrict__ A, const float* __restrict__ W,
    const float* __restrict__ bias, float* __restrict__ C,
    int M, int N, int K)
{
    __shared__ float As[16][132];
    __shared__ float Bs[16][132];

    const int t = threadIdx.x;
    const int nBase = blockIdx.x * 128;
    const int mBase = blockIdx.y * 128;
    const int m0 = (t >> 4) * 4;
    const int n0 = (t & 15) * 4;
    const int lrow = t >> 2;
    const int lcol = (t & 3) * 4;

    unsigned long long acc[8][4];
#pragma unroll
    for (int i = 0; i < 8; i++)
#pragma unroll
        for (int jj = 0; jj < 4; jj++) acc[i][jj] = 0ULL;

    const float* Aptr0 = A + (size_t)(mBase + lrow) * K + lcol;
    const float* Aptr1 = A + (size_t)(mBase + lrow + 64) * K + lcol;
    const float* Wptr0 = W + (size_t)(nBase + lrow) * K + lcol;
    const float* Wptr1 = W + (size_t)(nBase + lrow + 64) * K + lcol;

    for (int k0 = 0; k0 < K; k0 += 16) {
        float4 a0 = *(const float4*)(Aptr0 + k0);
        float4 a1 = *(const float4*)(Aptr1 + k0);
        float4 b0 = *(const float4*)(Wptr0 + k0);
        float4 b1 = *(const float4*)(Wptr1 + k0);
        __syncthreads();
        As[lcol + 0][lrow] = a0.x; As[lcol + 1][lrow] = a0.y;
        As[lcol + 2][lrow] = a0.z; As[lcol + 3][lrow] = a0.w;
        As[lcol + 0][lrow + 64] = a1.x; As[lcol + 1][lrow + 64] = a1.y;
        As[lcol + 2][lrow + 64] = a1.z; As[lcol + 3][lrow + 64] = a1.w;
        Bs[lcol + 0][lrow] = b0.x; Bs[lcol + 1][lrow] = b0.y;
        Bs[lcol + 2][lrow] = b0.z; Bs[lcol + 3][lrow] = b0.w;
        Bs[lcol + 0][lrow + 64] = b1.x; Bs[lcol + 1][lrow + 64] = b1.y;
        Bs[lcol + 2][lrow + 64] = b1.z; Bs[lcol + 3][lrow + 64] = b1.w;
        __syncthreads();

#pragma unroll
        for (int k = 0; k < 16; k++) {
            float4 av0 = *(const float4*)&As[k][m0];
            float4 av1 = *(const float4*)&As[k][m0 + 64];
            float4 bv0 = *(const float4*)&Bs[k][n0];
            float4 bv1 = *(const float4*)&Bs[k][n0 + 64];
            unsigned long long bp[4];
            bp[0] = pack2(bv0.x, bv0.y);
            bp[1] = pack2(bv0.z, bv0.w);
            bp[2] = pack2(bv1.x, bv1.y);
            bp[3] = pack2(bv1.z, bv1.w);
            float am[8] = {av0.x, av0.y, av0.z, av0.w,
                           av1.x, av1.y, av1.z, av1.w};
#pragma unroll
            for (int i = 0; i < 8; i++) {
                unsigned long long ad = pack2(am[i], am[i]);
#pragma unroll
                for (int jj = 0; jj < 4; jj++)
                    acc[i][jj] = ffma2(ad, bp[jj], acc[i][jj]);
            }
        }
    }

    float4 bias0 = *(const float4*)(bias + nBase + n0);
    float4 bias1 = *(const float4*)(bias + nBase + n0 + 64);
#pragma unroll
    for (int i = 0; i < 8; i++) {
        const int mg = mBase + m0 + ((i < 4) ? i : (i + 60));
        float2 p0 = unpack2(acc[i][0]);
        float2 p1 = unpack2(acc[i][1]);
        float2 p2 = unpack2(acc[i][2]);
        float2 p3 = unpack2(acc[i][3]);
        float4 o0 = make_float4(p0.x + bias0.x, p0.y + bias0.y,
                                p1.x + bias0.z, p1.y + bias0.w);
        float4 o1 = make_float4(p2.x + bias1.x, p2.y + bias1.y,
                                p3.x + bias1.z, p3.y + bias1.w);
        float* crow = C + (size_t)mg * N + nBase;
        *(float4*)(crow + n0) = o0;
        *(float4*)(crow + n0 + 64) = o1;
    }
}

// ---------------- pack W into hi/lo bf16 MMA B-fragments ----------------
// B frag m16n8k16 (col): lane l: n = fn*8 + (l>>2), k0 = fk*16 + 2*(l&3)
// regs: {W[n][k0],W[n][k0+1]} , {W[n][k0+8],W[n][k0+9]}
__global__ __launch_bounds__(256) void pack_b(
    const float* __restrict__ W, uint2* __restrict__ Bhi, uint2* __restrict__ Blo)
{
    const int gid = blockIdx.x * 256 + threadIdx.x;  // < 131072
    const int lane = gid & 31;
    const int fk = (gid >> 5) & 31;
    const int fn = gid >> 10;

    const int n = fn * 8 + (lane >> 2);
    const int k0 = fk * 16 + (lane & 3) * 2;
    const float* wr = W + (size_t)n * HH;
    float2 w01 = *(const float2*)(wr + k0);
    float2 w89 = *(const float2*)(wr + k0 + 8);

    uint32_t h0 = cvt_bf16x2(w01.x, w01.y);
    uint32_t h1 = cvt_bf16x2(w89.x, w89.y);
    float r0 = __uint_as_float(h0 << 16), r1 = __uint_as_float(h0 & 0xffff0000u);
    float r2 = __uint_as_float(h1 << 16), r3 = __uint_as_float(h1 & 0xffff0000u);
    uint32_t l0 = cvt_bf16x2(w01.x - r0, w01.y - r1);
    uint32_t l1 = cvt_bf16x2(w89.x - r2, w89.y - r3);

    Bhi[gid] = make_uint2(h0, h1);
    Blo[gid] = make_uint2(l0, l1);
}

// ---------------- pack A = tanh(e (+) d) into hi/lo bf16 A-fragments ----------
// A frag m16n8k16 (row): lane l: g = l>>2, k0 = fk*16 + 2*(l&3)
// regs: {A[g][k0],A[g][k0+1]}, {A[g+8][k0..]}, {A[g][k0+8..]}, {A[g+8][k0+8..]}
__global__ __launch_bounds__(256) void pack_a(
    const float* __restrict__ e, const float* __restrict__ dmat,
    uint4* __restrict__ Ahi, uint4* __restrict__ Alo)
{
    const int gid = blockIdx.x * 256 + threadIdx.x;  // < 8388608
    const int lane = gid & 31;
    const int fk = (gid >> 5) & 31;
    const int fm = gid >> 10;                         // < 8192

    const int g = lane >> 2;
    const int k0 = fk * 16 + (lane & 3) * 2;
    const int m0 = fm * 16 + g;        // row g ; row g+8 = m0+8 (same bt)
    const int bt = m0 >> 7;
    const int u0 = m0 & 127;
    const int b = bt >> 8;

    const float* erow = e + (size_t)bt * HH;
    const float* dr0 = dmat + (size_t)(b * 128 + u0) * HH;
    const float* dr1 = dr0 + 8 * HH;   // u0+8 (g<8 so u0+8 <= 127... u0 = (fm&7)*16+g)

    float2 e01 = *(const float2*)(erow + k0);
    float2 e89 = *(const float2*)(erow + k0 + 8);
    float2 d001 = *(const float2*)(dr0 + k0);
    float2 d089 = *(const float2*)(dr0 + k0 + 8);
    float2 d101 = *(const float2*)(dr1 + k0);
    float2 d189 = *(const float2*)(dr1 + k0 + 8);

    float x0 = tanh_apx(e01.x + d001.x), x1 = tanh_apx(e01.y + d001.y);
    float x8 = tanh_apx(e89.x + d089.x), x9 = tanh_apx(e89.y + d089.y);
    float y0 = tanh_apx(e01.x + d101.x), y1 = tanh_apx(e01.y + d101.y);
    float y8 = tanh_apx(e89.x + d189.x), y9 = tanh_apx(e89.y + d189.y);

    uint32_t h0 = cvt_bf16x2(x0, x1);
    uint32_t h1 = cvt_bf16x2(y0, y1);
    uint32_t h2 = cvt_bf16x2(x8, x9);
    uint32_t h3 = cvt_bf16x2(y8, y9);

    float t0 = __uint_as_float(h0 << 16), t1 = __uint_as_float(h0 & 0xffff0000u);
    float t2 = __uint_as_float(h1 << 16), t3 = __uint_as_float(h1 & 0xffff0000u);
    float t4 = __uint_as_float(h2 << 16), t5 = __uint_as_float(h2 & 0xffff0000u);
    float t6 = __uint_as_float(h3 << 16), t7 = __uint_as_float(h3 & 0xffff0000u);

    uint32_t l0 = cvt_bf16x2(x0 - t0, x1 - t1);
    uint32_t l1 = cvt_bf16x2(y0 - t2, y1 - t3);
    uint32_t l2 = cvt_bf16x2(x8 - t4, x9 - t5);
    uint32_t l3 = cvt_bf16x2(y8 - t6, y9 - t7);

    Ahi[gid] = make_uint4(h0, h1, h2, h3);
    Alo[gid] = make_uint4(l0, l1, l2, l3);
}

// ---------------- joint GEMM: out = A @ W^T + bias via HMMA 3-pass ----------
// CTA 128x128, 8 warps as 2(M) x 4(N); warp tile 64x32.
__global__ __launch_bounds__(256) void joint_gemm(
    const uint4* __restrict__ Ahi, const uint4* __restrict__ Alo,
    const uint2* __restrict__ Bhi, const uint2* __restrict__ Blo,
    const float* __restrict__ bias, float* __restrict__ out)
{
    const int tid = threadIdx.x;
    const int lane = tid & 31;
    const int wid = tid >> 5;
    const int wr = wid >> 2;            // 0..1  (64-row block)
    const int wc = wid & 3;             // 0..3  (32-col block)
    const int mt = blockIdx.y;          // 0..1023
    const int nt = blockIdx.x;          // 0..7

    const int fmBase = mt * 8 + wr * 4;
    const int fnBase = nt * 16 + wc * 4;

    float c[4][4][4];
#pragma unroll
    for (int i = 0; i < 4; i++)
#pragma unroll
        for (int j = 0; j < 4; j++)
#pragma unroll
            for (int q = 0; q < 4; q++) c[i][j][q] = 0.f;

    for (int fk = 0; fk < 32; fk++) {
        uint4 ah[4], al[4];
        uint2 bh[4], bl[4];
#pragma unroll
        for (int i = 0; i < 4; i++) {
            const size_t idx = ((size_t)(fmBase + i) * 32 + fk) * 32 + lane;
            ah[i] = __ldg(Ahi + idx);
            al[i] = __ldg(Alo + idx);
        }
#pragma unroll
        for (int j = 0; j < 4; j++) {
            const size_t idx = ((size_t)(fnBase + j) * 32 + fk) * 32 + lane;
            bh[j] = __ldg(Bhi + idx);
            bl[j] = __ldg(Blo + idx);
        }
        // pass 1: Ahi * Bhi   (16 independent MMAs)
#pragma unroll
        for (int i = 0; i < 4; i++)
#pragma unroll
            for (int j = 0; j < 4; j++)
                mma16816(c[i][j], (const uint32_t*)&ah[i], (const uint32_t*)&bh[j]);
        // pass 2: Ahi * Blo
#pragma unroll
        for (int i = 0; i < 4; i++)
#pragma unroll
            for (int j = 0; j < 4; j++)
                mma16816(c[i][j], (const uint32_t*)&ah[i], (const uint32_t*)&bl[j]);
        // pass 3: Alo * Bhi
#pragma unroll
        for (int i = 0; i < 4; i++)
#pragma unroll
            for (int j = 0; j < 4; j++)
                mma16816(c[i][j], (const uint32_t*)&al[i], (const uint32_t*)&bh[j]);
    }

    // epilogue: C frag lane mapping: rows g, g+8 ; cols 2t, 2t+1
    const int g = lane >> 2;
    const int t2 = (lane & 3) * 2;
#pragma unroll
    for (int j = 0; j < 4; j++) {
        const int col = nt * 128 + wc * 32 + j * 8 + t2;
        const float2 bv = *(const float2*)(bias + col);
#pragma unroll
        for (int i = 0; i < 4; i++) {
            const int row = mt * 128 + wr * 64 + i * 16 + g;
            float2 o0 = make_float2(c[i][j][0] + bv.x, c[i][j][1] + bv.y);
            float2 o1 = make_float2(c[i][j][2] + bv.x, c[i][j][3] + bv.y);
            *(float2*)(out + (size_t)row * VV + col) = o0;
            *(float2*)(out + (size_t)(row + 8) * VV + col) = o1;
        }
    }
}

// ---------------- launch ----------------
extern "C" void kernel_launch(void* const* d_in, const int* in_sizes, int n_in,
                              void* d_out, int out_size)
{
    const float* enc     = (const float*)d_in[0];
    const float* dec     = (const float*)d_in[1];
    const float* W_enc   = (const float*)d_in[2];
    const float* b_enc   = (const float*)d_in[3];
    const float* W_dec   = (const float*)d_in[4];
    const float* b_dec   = (const float*)d_in[5];
    const float* W_joint = (const float*)d_in[6];
    const float* b_joint = (const float*)d_in[7];
    float* out = (float*)d_out;

    float *e_ptr, *d_ptr;
    uint4 *ahi, *alo;
    uint2 *bhi, *blo;
    cudaGetSymbolAddress((void**)&e_ptr, g_e);
    cudaGetSymbolAddress((void**)&d_ptr, g_d);
    cudaGetSymbolAddress((void**)&ahi, g_Ahi);
    cudaGetSymbolAddress((void**)&alo, g_Alo);
    cudaGetSymbolAddress((void**)&bhi, g_Bhi);
    cudaGetSymbolAddress((void**)&blo, g_Blo);

    // W_joint -> fragment-ordered bf16 hi/lo
    pack_b<<<(VV / 8) * (HH / 16) * 32 / 256, 256>>>(W_joint, bhi, blo);
    // projections (fp32)
    sgemm_bias<<<dim3(4, 8), 256>>>(enc, W_enc, b_enc, e_ptr, BB * TT, HH, HH);
    sgemm_bias<<<dim3(4, 4), 256>>>(dec, W_dec, b_dec, d_ptr, BB * UU, HH, HH);
    // A = tanh(e (+) d) -> fragment-ordered bf16 hi/lo
    pack_a<<<(MM / 16) * (HH / 16) * 32 / 256, 256>>>(e_ptr, d_ptr, ahi, alo);
    // out = A @ W^T + bias
    joint_gemm<<<dim3(VV / 128, MM / 128), 256>>>(ahi, alo, bhi, blo, b_joint, out);
}